// round 1
// baseline (speedup 1.0000x reference)
#include <cuda_runtime.h>

#define N_USERS 100000
#define N_ITEMS 50000
#define NNZ_C   1600000
#define DIM     64

// Scratch for the dense-GEMM outputs (static __device__ arrays per the no-alloc rule)
__device__ float g_xw_user[(size_t)N_USERS * DIM];   // 25.6 MB
__device__ float g_xw_item[(size_t)N_ITEMS * DIM];   // 12.8 MB

// ---------------------------------------------------------------------------
// Dense GEMM: Y[r][c] = sum_k X[r][k] * W[k][c], K = N = 64.
// 64x64 output tile per 256-thread block, 4x4 register tile per thread.
// which == 0 -> write g_xw_user, which == 1 -> write g_xw_item.
// ---------------------------------------------------------------------------
__global__ __launch_bounds__(256) void gemm64_kernel(
    const float* __restrict__ X, const float* __restrict__ W,
    int nrows, int which)
{
    __shared__ float Ws[64 * 64];     // W as-is: [k][c]
    __shared__ float Xt[64 * 68];     // X transposed: [k][r], stride 68 (272B, 16B-aligned)

    const int tid  = threadIdx.x;
    const int row0 = blockIdx.x * 64;

    // Load W (4096 floats) with float4
    {
        const float4* W4  = (const float4*)W;
        float4*       Ws4 = (float4*)Ws;
        #pragma unroll
        for (int i = 0; i < 4; i++) Ws4[tid + i * 256] = W4[tid + i * 256];
    }
    // Load X tile (64 rows x 64 cols) transposed into Xt, zero-pad past nrows
    #pragma unroll
    for (int i = 0; i < 4; i++) {
        int idx = tid + i * 256;           // float4 index within tile
        int r   = idx >> 4;                // 0..63
        int k4  = (idx & 15) * 4;          // 0,4,..,60
        float4 v = make_float4(0.f, 0.f, 0.f, 0.f);
        if (row0 + r < nrows)
            v = *(const float4*)(X + (size_t)(row0 + r) * DIM + k4);
        Xt[(k4 + 0) * 68 + r] = v.x;
        Xt[(k4 + 1) * 68 + r] = v.y;
        Xt[(k4 + 2) * 68 + r] = v.z;
        Xt[(k4 + 3) * 68 + r] = v.w;
    }
    __syncthreads();

    const int tx = tid & 15;   // col group: cols tx*4 .. tx*4+3
    const int ty = tid >> 4;   // row group: rows ty*4 .. ty*4+3

    float acc[4][4] = {};
    #pragma unroll 16
    for (int k = 0; k < 64; k++) {
        float4 a = *(const float4*)&Xt[k * 68 + ty * 4];
        float4 b = *(const float4*)&Ws[k * 64 + tx * 4];
        float av[4] = {a.x, a.y, a.z, a.w};
        float bv[4] = {b.x, b.y, b.z, b.w};
        #pragma unroll
        for (int i = 0; i < 4; i++)
            #pragma unroll
            for (int j = 0; j < 4; j++)
                acc[i][j] += av[i] * bv[j];
    }

    float* Y = which ? g_xw_item : g_xw_user;
    #pragma unroll
    for (int i = 0; i < 4; i++) {
        int r = row0 + ty * 4 + i;
        if (r < nrows) {
            *(float4*)(Y + (size_t)r * DIM + tx * 4) =
                make_float4(acc[i][0], acc[i][1], acc[i][2], acc[i][3]);
        }
    }
}

// ---------------------------------------------------------------------------
// SpMM scatter (both directions fused):
//   out_user[r] += v * xw_item[c]   (lanes 0..15, 4 floats each)
//   out_item[c] += v * xw_user[r]   (lanes 16..31, 4 floats each)
// One warp loads 32 edges' (r,c,v) coalesced, then broadcasts each edge via
// shfl and does one red.global.add.v4.f32 per half-warp lane.
// NNZ is a multiple of 32, so no tail handling needed.
// ---------------------------------------------------------------------------
__global__ __launch_bounds__(256) void spmm_scatter_kernel(
    const int* __restrict__ rows, const int* __restrict__ cols,
    const float* __restrict__ vals,
    float* __restrict__ out_user, float* __restrict__ out_item)
{
    const int lane  = threadIdx.x & 31;
    const int warp  = (blockIdx.x * blockDim.x + threadIdx.x) >> 5;
    const int nwarp = (gridDim.x * blockDim.x) >> 5;

    for (int base = warp * 32; base < NNZ_C; base += nwarp * 32) {
        const int e = base + lane;
        const int   r = rows[e];
        const int   c = cols[e];
        const float v = vals[e];

        #pragma unroll 1
        for (int j = 0; j < 32; j++) {
            const int   rj = __shfl_sync(0xffffffffu, r, j);
            const int   cj = __shfl_sync(0xffffffffu, c, j);
            const float vj = __shfl_sync(0xffffffffu, v, j);

            const float* src;
            float*       dst;
            int          l;
            if (lane < 16) {
                l   = lane;
                src = g_xw_item + (size_t)cj * DIM;
                dst = out_user  + (size_t)rj * DIM;
            } else {
                l   = lane - 16;
                src = g_xw_user + (size_t)rj * DIM;
                dst = out_item  + (size_t)cj * DIM;
            }
            float4 s = __ldg((const float4*)src + l);
            asm volatile(
                "red.global.add.v4.f32 [%0], {%1, %2, %3, %4};"
                :: "l"(dst + l * 4),
                   "f"(vj * s.x), "f"(vj * s.y), "f"(vj * s.z), "f"(vj * s.w)
                : "memory");
        }
    }
}

// ---------------------------------------------------------------------------
// In-place ReLU over the whole output (float4 grid-stride-free, exact count)
// ---------------------------------------------------------------------------
__global__ __launch_bounds__(256) void relu_kernel(float* __restrict__ out, int n4)
{
    int i = blockIdx.x * blockDim.x + threadIdx.x;
    if (i < n4) {
        float4 v = ((const float4*)out)[i];
        v.x = fmaxf(v.x, 0.f);
        v.y = fmaxf(v.y, 0.f);
        v.z = fmaxf(v.z, 0.f);
        v.w = fmaxf(v.w, 0.f);
        ((float4*)out)[i] = v;
    }
}

extern "C" void kernel_launch(void* const* d_in, const int* in_sizes, int n_in,
                              void* d_out, int out_size)
{
    const float* user_x   = (const float*)d_in[0];
    const float* item_x   = (const float*)d_in[1];
    const float* user_w   = (const float*)d_in[2];
    const float* item_w   = (const float*)d_in[3];
    const int*   ui_rows  = (const int*)d_in[4];
    const int*   ui_cols  = (const int*)d_in[5];
    const float* ui_vals  = (const float*)d_in[6];

    float* out      = (float*)d_out;
    float* out_user = out;
    float* out_item = out + (size_t)N_USERS * DIM;

    // Zero the accumulation output (graph-capturable memset node)
    cudaMemsetAsync(d_out, 0, (size_t)(N_USERS + N_ITEMS) * DIM * sizeof(float), 0);

    // Dense GEMMs -> scratch
    gemm64_kernel<<<(N_USERS + 63) / 64, 256>>>(user_x, user_w, N_USERS, 0);
    gemm64_kernel<<<(N_ITEMS + 63) / 64, 256>>>(item_x, item_w, N_ITEMS, 1);

    // Fused bidirectional scatter
    spmm_scatter_kernel<<<1184, 256>>>(ui_rows, ui_cols, ui_vals, out_user, out_item);

    // ReLU epilogue
    const int n4 = (N_USERS + N_ITEMS) * DIM / 4;   // 2,400,000
    relu_kernel<<<(n4 + 255) / 256, 256>>>(out, n4);
}

// round 2
// speedup vs baseline: 1.1075x; 1.1075x over previous
#include <cuda_runtime.h>

#define N_USERS 100000
#define N_ITEMS 50000
#define N_ROWS  150000          // users then items, matching d_out layout
#define NNZ_C   1600000
#define DIM     64

#define CHUNK   1024
#define NBLK    147             // ceil(150000 / 1024)

// ---- device scratch (no-alloc rule) ----
__device__ float g_xw_user[(size_t)N_USERS * DIM];   // 25.6 MB
__device__ float g_xw_item[(size_t)N_ITEMS * DIM];   // 12.8 MB
__device__ int   g_cnt[N_ROWS];
__device__ int   g_off[N_ROWS + 1];
__device__ int   g_cur[N_ROWS];
__device__ int   g_partial[256];
__device__ int2  g_perm[2 * NNZ_C];                  // 25.6 MB: (src_idx, val-bits)

// ---------------------------------------------------------------------------
// Dense GEMM: Y = X @ W, K = N = 64. 64x64 tile/block, 4x4 per thread.
// ---------------------------------------------------------------------------
__global__ __launch_bounds__(256) void gemm64_kernel(
    const float* __restrict__ X, const float* __restrict__ W,
    int nrows, int which)
{
    __shared__ float Ws[64 * 64];
    __shared__ float Xt[64 * 68];

    const int tid  = threadIdx.x;
    const int row0 = blockIdx.x * 64;

    {
        const float4* W4  = (const float4*)W;
        float4*       Ws4 = (float4*)Ws;
        #pragma unroll
        for (int i = 0; i < 4; i++) Ws4[tid + i * 256] = W4[tid + i * 256];
    }
    #pragma unroll
    for (int i = 0; i < 4; i++) {
        int idx = tid + i * 256;
        int r   = idx >> 4;
        int k4  = (idx & 15) * 4;
        float4 v = make_float4(0.f, 0.f, 0.f, 0.f);
        if (row0 + r < nrows)
            v = *(const float4*)(X + (size_t)(row0 + r) * DIM + k4);
        Xt[(k4 + 0) * 68 + r] = v.x;
        Xt[(k4 + 1) * 68 + r] = v.y;
        Xt[(k4 + 2) * 68 + r] = v.z;
        Xt[(k4 + 3) * 68 + r] = v.w;
    }
    __syncthreads();

    const int tx = tid & 15;
    const int ty = tid >> 4;

    float acc[4][4] = {};
    #pragma unroll 16
    for (int k = 0; k < 64; k++) {
        float4 a = *(const float4*)&Xt[k * 68 + ty * 4];
        float4 b = *(const float4*)&Ws[k * 64 + tx * 4];
        float av[4] = {a.x, a.y, a.z, a.w};
        float bv[4] = {b.x, b.y, b.z, b.w};
        #pragma unroll
        for (int i = 0; i < 4; i++)
            #pragma unroll
            for (int j = 0; j < 4; j++)
                acc[i][j] += av[i] * bv[j];
    }

    float* Y = which ? g_xw_item : g_xw_user;
    #pragma unroll
    for (int i = 0; i < 4; i++) {
        int r = row0 + ty * 4 + i;
        if (r < nrows)
            *(float4*)(Y + (size_t)r * DIM + tx * 4) =
                make_float4(acc[i][0], acc[i][1], acc[i][2], acc[i][3]);
    }
}

// ---------------------------------------------------------------------------
// 1) Degree histogram over combined row space
// ---------------------------------------------------------------------------
__global__ __launch_bounds__(256) void hist_kernel(
    const int* __restrict__ rows, const int* __restrict__ cols)
{
    int e = blockIdx.x * blockDim.x + threadIdx.x;
    if (e >= NNZ_C) return;
    atomicAdd(&g_cnt[rows[e]], 1);
    atomicAdd(&g_cnt[N_USERS + cols[e]], 1);
}

// ---------------------------------------------------------------------------
// 2) Exclusive scan of g_cnt -> g_off (3 kernels)
// ---------------------------------------------------------------------------
__global__ __launch_bounds__(256) void scanA_kernel()
{
    __shared__ int sh[8];
    int b = blockIdx.x, t = threadIdx.x;
    int base = b * CHUNK + t * 4;
    int s = 0;
    #pragma unroll
    for (int i = 0; i < 4; i++) {
        int idx = base + i;
        if (idx < N_ROWS) s += g_cnt[idx];
    }
    #pragma unroll
    for (int o = 16; o > 0; o >>= 1) s += __shfl_down_sync(0xffffffffu, s, o);
    if ((t & 31) == 0) sh[t >> 5] = s;
    __syncthreads();
    if (t < 8) {
        int v = sh[t];
        #pragma unroll
        for (int o = 4; o > 0; o >>= 1) v += __shfl_down_sync(0xffu, v, o);
        if (t == 0) g_partial[b] = v;
    }
}

__global__ __launch_bounds__(256) void scanB_kernel()
{
    __shared__ int sh[256];
    int t = threadIdx.x;
    int v = (t < NBLK) ? g_partial[t] : 0;
    sh[t] = v;
    __syncthreads();
    for (int o = 1; o < 256; o <<= 1) {
        int x = (t >= o) ? sh[t - o] : 0;
        __syncthreads();
        sh[t] += x;
        __syncthreads();
    }
    int incl = sh[t];
    if (t < NBLK) g_partial[t] = incl - v;      // exclusive
    if (t == 255) g_off[N_ROWS] = incl;         // grand total = 2*NNZ
}

__global__ __launch_bounds__(256) void scanC_kernel()
{
    __shared__ int warpsum[8];
    int b = blockIdx.x, t = threadIdx.x;
    int base = b * CHUNK + t * 4;
    int c[4]; int s = 0;
    #pragma unroll
    for (int i = 0; i < 4; i++) {
        int idx = base + i;
        c[i] = (idx < N_ROWS) ? g_cnt[idx] : 0;
        s += c[i];
    }
    int lane = t & 31, w = t >> 5;
    int incl = s;
    #pragma unroll
    for (int o = 1; o < 32; o <<= 1) {
        int x = __shfl_up_sync(0xffffffffu, incl, o);
        if (lane >= o) incl += x;
    }
    if (lane == 31) warpsum[w] = incl;
    __syncthreads();
    if (t < 8) {
        int v  = warpsum[t];
        int iv = v;
        #pragma unroll
        for (int o = 1; o < 8; o <<= 1) {
            int x = __shfl_up_sync(0xffu, iv, o);
            if (t >= o) iv += x;
        }
        warpsum[t] = iv - v;                    // exclusive within block
    }
    __syncthreads();
    int excl = incl - s + warpsum[w] + g_partial[b];
    #pragma unroll
    for (int i = 0; i < 4; i++) {
        int idx = base + i;
        if (idx < N_ROWS) { g_off[idx] = excl; excl += c[i]; }
    }
}

// ---------------------------------------------------------------------------
// 3) Permute edges into bucketed layout: (source row index, value)
// ---------------------------------------------------------------------------
__global__ __launch_bounds__(256) void permute_kernel(
    const int* __restrict__ rows, const int* __restrict__ cols,
    const float* __restrict__ vals)
{
    int e = blockIdx.x * blockDim.x + threadIdx.x;
    if (e >= NNZ_C) return;
    int   r = rows[e];
    int   c = cols[e];
    float v = vals[e];
    int p0 = atomicAdd(&g_cur[r], 1);
    g_perm[p0] = make_int2(c, __float_as_int(v));
    int p1 = atomicAdd(&g_cur[N_USERS + c], 1);
    g_perm[p1] = make_int2(r, __float_as_int(v));
}

// ---------------------------------------------------------------------------
// 4) SpMM gather: one warp per output row. Register accumulation, fused ReLU.
//    out row i < 100000 gathers from g_xw_item; else from g_xw_user.
// ---------------------------------------------------------------------------
__global__ __launch_bounds__(256) void spmm_gather_kernel(float* __restrict__ out)
{
    const int wid  = (blockIdx.x * blockDim.x + threadIdx.x) >> 5;
    const int lane = threadIdx.x & 31;
    if (wid >= N_ROWS) return;

    const int start = g_off[wid];
    const int end   = g_off[wid + 1];
    const float* __restrict__ src = (wid < N_USERS) ? g_xw_item : g_xw_user;

    float a0 = 0.f, a1 = 0.f;
    for (int e = start; e < end; e += 32) {
        const int nedge = min(32, end - e);
        int2 p = make_int2(0, 0);
        if (lane < nedge) p = g_perm[e + lane];
        #pragma unroll 4
        for (int j = 0; j < nedge; j++) {
            int   idx = __shfl_sync(0xffffffffu, p.x, j);
            float v   = __int_as_float(__shfl_sync(0xffffffffu, p.y, j));
            float2 s  = __ldg((const float2*)(src + (size_t)idx * DIM) + lane);
            a0 += v * s.x;
            a1 += v * s.y;
        }
    }
    float2 o;
    o.x = fmaxf(a0, 0.f);
    o.y = fmaxf(a1, 0.f);
    *((float2*)(out + (size_t)wid * DIM) + lane) = o;
}

// ---------------------------------------------------------------------------
extern "C" void kernel_launch(void* const* d_in, const int* in_sizes, int n_in,
                              void* d_out, int out_size)
{
    const float* user_x  = (const float*)d_in[0];
    const float* item_x  = (const float*)d_in[1];
    const float* user_w  = (const float*)d_in[2];
    const float* item_w  = (const float*)d_in[3];
    const int*   ui_rows = (const int*)d_in[4];
    const int*   ui_cols = (const int*)d_in[5];
    const float* ui_vals = (const float*)d_in[6];

    float* out = (float*)d_out;

    void *p_cnt = nullptr, *p_off = nullptr, *p_cur = nullptr;
    cudaGetSymbolAddress(&p_cnt, g_cnt);
    cudaGetSymbolAddress(&p_off, g_off);
    cudaGetSymbolAddress(&p_cur, g_cur);

    // zero degree counters
    cudaMemsetAsync(p_cnt, 0, N_ROWS * sizeof(int), 0);

    // dense GEMMs -> scratch
    gemm64_kernel<<<(N_USERS + 63) / 64, 256>>>(user_x, user_w, N_USERS, 0);
    gemm64_kernel<<<(N_ITEMS + 63) / 64, 256>>>(item_x, item_w, N_ITEMS, 1);

    // CSR-ish build
    hist_kernel<<<(NNZ_C + 255) / 256, 256>>>(ui_rows, ui_cols);
    scanA_kernel<<<NBLK, 256>>>();
    scanB_kernel<<<1, 256>>>();
    scanC_kernel<<<NBLK, 256>>>();
    cudaMemcpyAsync(p_cur, p_off, N_ROWS * sizeof(int),
                    cudaMemcpyDeviceToDevice, 0);
    permute_kernel<<<(NNZ_C + 255) / 256, 256>>>(ui_rows, ui_cols, ui_vals);

    // gather SpMM with fused ReLU (writes every output row -> no memset needed)
    spmm_gather_kernel<<<(N_ROWS * 32 + 255) / 256, 256>>>(out);
}